// round 15
// baseline (speedup 1.0000x reference)
#include <cuda_runtime.h>
#include <cstdint>

// out[n,c,oh,ow] = x[n,c,2*oh,2*ow]
//   x:   (8,128,512,512) fp32, contiguous NCHW  -> 268,435,456 elems
//   out: (8,128,256,256) fp32                    ->  67,108,864 elems
//
// Persistent variant of the R12 winner. One WARP per output row per
// iteration; warps grid-stride over all 262,144 rows so the launch is a
// single wave (148 SMs x 4 CTAs x 512 thr = 592 CTAs) — no CTA
// launch/drain churn across ~14 waves.
// Per iteration the access pattern is identical to R12: lane k loads
// contiguous float4 irow[k + 32*j] (fully coalesced, dense 512B/warp/LDG);
// the even elements (.x,.z) of lane k's float4 are exactly output floats
// 2k,2k+1 = output float2 index k — deinterleave is free, no shuffles.
// 4 independent front-batched loads, 4 coalesced STG.64, streaming hints.

static constexpr int OUT_ROWS   = 8 * 128 * 256;  // 262,144 output rows
static constexpr int IN_ROW_F4  = 128;            // float4 per input row
static constexpr int OUT_ROW_F2 = 128;            // float2 per output row
static constexpr int THREADS    = 512;            // 16 warps per block
static constexpr int NUM_SMS    = 148;
// 512 thr = 16 warps; 64 warps/SM -> 4 resident CTAs/SM. One full wave:
static constexpr int GRID = NUM_SMS * 4;          // 592 CTAs

__global__ __launch_bounds__(THREADS) void strided_slice_kernel(
    const float4* __restrict__ in, float2* __restrict__ out)
{
    int lane   = threadIdx.x & 31;
    int warp0  = (blockIdx.x * blockDim.x + threadIdx.x) >> 5;  // starting row
    int nwarps = (GRID * THREADS) >> 5;                         // 9,472 warps

    for (int r = warp0; r < OUT_ROWS; r += nwarps) {
        const float4* irow = in  + (long)r * (2 * IN_ROW_F4);
        float2*       orow = out + (long)r * OUT_ROW_F2;

        // 4 independent, warp-contiguous 128-bit streaming loads
        float4 a = __ldcs(irow + lane);
        float4 b = __ldcs(irow + lane + 32);
        float4 c = __ldcs(irow + lane + 64);
        float4 d = __ldcs(irow + lane + 96);

        // even elements -> output float2 at same lane index: free deinterleave
        __stcs(orow + lane,      make_float2(a.x, a.z));
        __stcs(orow + lane + 32, make_float2(b.x, b.z));
        __stcs(orow + lane + 64, make_float2(c.x, c.z));
        __stcs(orow + lane + 96, make_float2(d.x, d.z));
    }
}

extern "C" void kernel_launch(void* const* d_in, const int* in_sizes, int n_in,
                              void* d_out, int out_size)
{
    const float4* in  = (const float4*)d_in[0];
    float2*       out = (float2*)d_out;

    strided_slice_kernel<<<GRID, THREADS>>>(in, out);
}